// round 15
// baseline (speedup 1.0000x reference)
#include <cuda_runtime.h>
#include <cuda_fp16.h>
#include <cstdint>
#include <math.h>

#define DIN  768
#define DHID 256
#define NREL 2
#define MAXN 50000
#define MAXE 800000

// ---------------- scratch (device globals) ------------------------------------
__device__ float g_H1[(size_t)MAXN * DIN];    // halves: XH [N,768] | H1f [N,768]
__device__ float g_T [(size_t)MAXN * 768];    // TR fp32 [N,256] + TM half [N,512]
__device__ float g_X [(size_t)MAXN * DHID];   // Xh half [N,256]
__device__ float g_F [(size_t)MAXN * DHID];   // fc2 output fp32 [N,256]
__device__ float g_RW[1441792];               // fp16 weights (as half storage)
__device__ int   g_CNT[MAXN * NREL];
__device__ int   g_OFF[MAXN * NREL];
__device__ int   g_CUR[MAXN * NREL];
__device__ int   g_SRC[MAXE];
__device__ int   g_TOTAL[1];
__device__ int   g_flag[1];

// offsets into weight buffer (halves)
#define OFF_FC1   0           // [768x768]
#define OFF_WR1   589824      // [768x256]
#define OFF_WM1   786432      // [768x512]
#define OFF_WR2   1179648     // [256x256]
#define OFF_WM2   1245184     // [256x512]
#define OFF_FC2   1376256     // [256x256]

// ---------------- helpers ------------------------------------------------------
__device__ __forceinline__ void mma16816(float* c, const uint32_t* a, const uint32_t* b) {
    asm volatile("mma.sync.aligned.m16n8k16.row.col.f32.f16.f16.f32 "
                 "{%0,%1,%2,%3}, {%4,%5,%6,%7}, {%8,%9}, {%0,%1,%2,%3};"
                 : "+f"(c[0]), "+f"(c[1]), "+f"(c[2]), "+f"(c[3])
                 : "r"(a[0]), "r"(a[1]), "r"(a[2]), "r"(a[3]), "r"(b[0]), "r"(b[1]));
}
__device__ __forceinline__ void cpasync16(uint32_t saddr, const void* gptr, uint32_t sz) {
    asm volatile("cp.async.ca.shared.global [%0], [%1], 16, %2;"
                 :: "r"(saddr), "l"(gptr), "r"(sz) : "memory");
}
__device__ __forceinline__ uint32_t smem_u32(const void* p) {
    uint32_t a;
    asm("{ .reg .u64 t; cvta.to.shared.u64 t, %1; cvt.u32.u64 %0, t; }" : "=r"(a) : "l"(p));
    return a;
}

// ---------------- fp16 mma.sync GEMM: 128x256 block, 64x64 warp tile -----------
// BK=32 halves. cp.async 3-stage ring (2 CTAs/SM); ldmatrix.x4 A, ldmatrix.x4.trans B.
// EPI: 0 none, 1 +bias, 2 +bias+leaky. OUTH: 1 = half output, 0 = fp32.
#define APADH 40      // A row stride in halves (32 + 8) -> 80B
#define BPADH 264     // B row stride in halves (256 + 8) -> 528B
#define BN    256
#define STAGES 3
#define ASZH (128 * APADH)          // halves
#define BSZH (32 * BPADH)
#define GEMM_SMEM (STAGES * (ASZH + BSZH) * 2)

template<int EPI, int OUTH>
__global__ void __launch_bounds__(256, 2)
gemm_f16_kernel(const __half* __restrict__ A, const __half* __restrict__ B,
                void* __restrict__ Cv, const float* __restrict__ bias,
                int M, int K, int ldb, int ldc) {
    extern __shared__ __half smh[];
    const uint32_t smem_base = smem_u32(smh);

    const int tid  = threadIdx.x;
    const int w    = tid >> 5;
    const int lane = tid & 31;
    const int g    = lane >> 2;
    const int cq   = lane & 3;
    const int wm   = w >> 2;      // 0..1
    const int wn   = w & 3;       // 0..3
    const int row0 = blockIdx.x * 128;
    const int col0 = blockIdx.y * BN;

    // A fill: 128 rows x 64B = 512 x 16B chunks, 2/thread
    const int ar  = tid >> 2;
    const int ac16 = tid & 3;
    const uint32_t aoff0 = (uint32_t)(ar * 80 + ac16 * 16);
    const uint32_t aoff1 = aoff0 + 64u * 80u;
    const int gr0 = row0 + ar, gr1 = row0 + ar + 64;
    const uint32_t sz0 = (gr0 < M) ? 16u : 0u;
    const uint32_t sz1 = (gr1 < M) ? 16u : 0u;
    const __half* agp0 = A + (size_t)(gr0 < M ? gr0 : 0) * K + ac16 * 8;
    const __half* agp1 = A + (size_t)(gr1 < M ? gr1 : 0) * K + ac16 * 8;

    // B fill: 32 rows x 512B = 1024 x 16B chunks, 4/thread
    uint32_t boff[4];
    const __half* bgp[4];
    #pragma unroll
    for (int it = 0; it < 4; it++) {
        int idx = tid + it * 256;
        int brow = idx >> 5, bc16 = idx & 31;
        boff[it] = (uint32_t)(brow * 528 + bc16 * 16);
        bgp[it]  = B + (size_t)brow * ldb + col0 + bc16 * 8;
    }
    const size_t bstep = (size_t)32 * ldb;

    // ldmatrix A lane mapping
    const int lm_mat  = lane >> 3;
    const int lm_row  = (lane & 7) + ((lm_mat & 1) << 3);
    const int lm_koff = (lm_mat >> 1) * 8;                      // halves
    const uint32_t a_lm_off = (uint32_t)(((wm * 64 + lm_row) * APADH + lm_koff) * 2);

    // ldmatrix B trans lane mapping
    const int b_krow = ((lm_mat & 1) << 3) + (lane & 7);
    const int b_coff = (lm_mat >> 1) * 8;                        // halves
    const uint32_t b_lm_base = (uint32_t)((b_krow * BPADH + wn * 64 + b_coff) * 2);

    const int nk = K >> 5;   // K/32

    auto issue_stage = [&](int s, int t) {
        uint32_t abase = smem_base + (uint32_t)(s * ASZH) * 2;
        uint32_t bbase = smem_base + (uint32_t)(STAGES * ASZH + s * BSZH) * 2;
        cpasync16(abase + aoff0, agp0 + t * 32, sz0);
        cpasync16(abase + aoff1, agp1 + t * 32, sz1);
        #pragma unroll
        for (int it = 0; it < 4; it++)
            cpasync16(bbase + boff[it], bgp[it] + (size_t)t * bstep, 16u);
        asm volatile("cp.async.commit_group;" ::: "memory");
    };

    float acc[4][8][4];
    #pragma unroll
    for (int mi = 0; mi < 4; mi++)
        #pragma unroll
        for (int ni = 0; ni < 8; ni++)
            #pragma unroll
            for (int q = 0; q < 4; q++) acc[mi][ni][q] = 0.f;

    issue_stage(0, 0);
    if (nk > 1) issue_stage(1, 1); else asm volatile("cp.async.commit_group;" ::: "memory");

    for (int t = 0; t < nk; t++) {
        if (t + 1 < nk)      { asm volatile("cp.async.wait_group 1;" ::: "memory"); }
        else                 { asm volatile("cp.async.wait_group 0;" ::: "memory"); }
        __syncthreads();
        if (t + 2 < nk) issue_stage((t + 2) % STAGES, t + 2);

        const int s = t % STAGES;
        const uint32_t aS = smem_base + (uint32_t)(s * ASZH) * 2;
        const uint32_t bS = smem_base + (uint32_t)(STAGES * ASZH + s * BSZH) * 2;

        #pragma unroll
        for (int k16 = 0; k16 < 2; k16++) {
            uint32_t af[4][4];
            #pragma unroll
            for (int mi = 0; mi < 4; mi++) {
                uint32_t addr = aS + a_lm_off + (uint32_t)((mi * 16 * APADH + k16 * 16) * 2);
                asm volatile("ldmatrix.sync.aligned.m8n8.x4.shared.b16 {%0,%1,%2,%3}, [%4];"
                    : "=r"(af[mi][0]), "=r"(af[mi][1]), "=r"(af[mi][2]), "=r"(af[mi][3])
                    : "r"(addr));
            }
            uint32_t bf[8][2];
            #pragma unroll
            for (int p = 0; p < 4; p++) {
                uint32_t addr = bS + b_lm_base + (uint32_t)((k16 * 16 * BPADH + p * 16) * 2);
                asm volatile("ldmatrix.sync.aligned.m8n8.x4.trans.shared.b16 {%0,%1,%2,%3}, [%4];"
                    : "=r"(bf[2 * p][0]), "=r"(bf[2 * p][1]),
                      "=r"(bf[2 * p + 1][0]), "=r"(bf[2 * p + 1][1])
                    : "r"(addr));
            }
            #pragma unroll
            for (int mi = 0; mi < 4; mi++)
                #pragma unroll
                for (int ni = 0; ni < 8; ni++)
                    mma16816(acc[mi][ni], af[mi], bf[ni]);
        }
        // no trailing barrier: top barrier of next iter orders buffer reuse
        // (issue at iter t targets stage (t+2)%3 == (t-1)%3, read-complete by this iter's barrier)
    }

    #pragma unroll
    for (int mi = 0; mi < 4; mi++) {
        int rbase = row0 + wm * 64 + mi * 16;
        int r0 = rbase + g, r1 = rbase + g + 8;
        #pragma unroll
        for (int ni = 0; ni < 8; ni++) {
            int col = col0 + wn * 64 + ni * 8 + cq * 2;
            float b0 = 0.f, b1 = 0.f;
            if (EPI >= 1) { b0 = bias[col]; b1 = bias[col + 1]; }
            float v0 = acc[mi][ni][0] + b0, v1 = acc[mi][ni][1] + b1;
            float v2 = acc[mi][ni][2] + b0, v3 = acc[mi][ni][3] + b1;
            if (EPI == 2) {
                v0 = v0 >= 0.f ? v0 : 0.01f * v0;
                v1 = v1 >= 0.f ? v1 : 0.01f * v1;
                v2 = v2 >= 0.f ? v2 : 0.01f * v2;
                v3 = v3 >= 0.f ? v3 : 0.01f * v3;
            }
            if (OUTH) {
                __half* Ch = (__half*)Cv;
                if (r0 < M) *(__half2*)(Ch + (size_t)r0 * ldc + col) = __floats2half2_rn(v0, v1);
                if (r1 < M) *(__half2*)(Ch + (size_t)r1 * ldc + col) = __floats2half2_rn(v2, v3);
            } else {
                float* C = (float*)Cv;
                if (r0 < M) *(float2*)(C + (size_t)r0 * ldc + col) = make_float2(v0, v1);
                if (r1 < M) *(float2*)(C + (size_t)r1 * ldc + col) = make_float2(v2, v3);
            }
        }
    }
}

// ---------------- fp32 -> fp16 conversion kernels ------------------------------
__global__ void f2h_kernel(const float4* __restrict__ src, uint2* __restrict__ dst,
                           long long n4) {
    long long i = (long long)blockIdx.x * blockDim.x + threadIdx.x;
    if (i < n4) {
        float4 v = src[i];
        __half2 h0 = __floats2half2_rn(v.x, v.y);
        __half2 h1 = __floats2half2_rn(v.z, v.w);
        dst[i] = make_uint2(*(uint32_t*)&h0, *(uint32_t*)&h1);
    }
}
// [K x 256] fp32 -> half into 512-wide buffer at column block (dst uint2 units)
__global__ void f2h_block512_kernel(const float4* __restrict__ src, uint2* __restrict__ dst,
                                    int n4, int cb4) {   // n4 = K*64, cb4 = colblock/4
    int i = blockIdx.x * blockDim.x + threadIdx.x;
    if (i >= n4) return;
    int row = i >> 6, c = i & 63;
    float4 v = src[i];
    __half2 h0 = __floats2half2_rn(v.x, v.y);
    __half2 h1 = __floats2half2_rn(v.z, v.w);
    dst[row * 128 + cb4 + c] = make_uint2(*(uint32_t*)&h0, *(uint32_t*)&h1);
}

// ---------------- edge machinery ----------------------------------------------
__global__ void probe_kernel(const long long* __restrict__ ei, long long Nn) {
    if (blockIdx.x == 0 && threadIdx.x == 0) {
        int ok = 1;
        for (int i = 0; i < 16; i++) {
            long long v = ei[i];
            if (v < 0 || v >= Nn) ok = 0;
        }
        g_flag[0] = ok;
        g_TOTAL[0] = 0;
    }
}
__global__ void zero_i_kernel(int* __restrict__ p, int n) {
    int i = blockIdx.x * blockDim.x + threadIdx.x;
    if (i < n) p[i] = 0;
}
__global__ void count_kernel(const int* __restrict__ ei32, const long long* __restrict__ ei64,
                             const int* __restrict__ et32, const long long* __restrict__ et64,
                             int* __restrict__ cnt, int E) {
    int e = blockIdx.x * blockDim.x + threadIdx.x;
    if (e >= E) return;
    long long dst; int r;
    if (g_flag[0]) { dst = ei64[(long long)E + e]; r = (int)et64[e]; }
    else           { dst = ei32[E + e];            r = et32[e]; }
    atomicAdd(&cnt[(int)dst * NREL + r], 1);
}
__global__ void scan_kernel(const int* __restrict__ cnt, int* __restrict__ off,
                            int* __restrict__ total, int n) {
    __shared__ int sh[256];
    __shared__ int base_sh;
    int i = blockIdx.x * 256 + threadIdx.x;
    int v = (i < n) ? cnt[i] : 0;
    sh[threadIdx.x] = v;
    __syncthreads();
    #pragma unroll
    for (int d = 1; d < 256; d <<= 1) {
        int t = (threadIdx.x >= d) ? sh[threadIdx.x - d] : 0;
        __syncthreads();
        sh[threadIdx.x] += t;
        __syncthreads();
    }
    if (threadIdx.x == 255) base_sh = atomicAdd(total, sh[255]);
    __syncthreads();
    if (i < n) off[i] = base_sh + sh[threadIdx.x] - v;
}
__global__ void copy_i_kernel(const int* __restrict__ s, int* __restrict__ d, int n) {
    int i = blockIdx.x * blockDim.x + threadIdx.x;
    if (i < n) d[i] = s[i];
}
__global__ void fill_kernel(const int* __restrict__ ei32, const long long* __restrict__ ei64,
                            const int* __restrict__ et32, const long long* __restrict__ et64,
                            int* __restrict__ cur, int* __restrict__ srcidx, int E) {
    int e = blockIdx.x * blockDim.x + threadIdx.x;
    if (e >= E) return;
    long long src, dst; int r;
    if (g_flag[0]) { src = ei64[e]; dst = ei64[(long long)E + e]; r = (int)et64[e]; }
    else           { src = ei32[e]; dst = ei32[E + e];            r = et32[e]; }
    int p = atomicAdd(&cur[(int)dst * NREL + r], 1);
    srcidx[p] = (int)src;
}

// ---------------- fused gather (fp16 msgs) + mean + fp32 root -> fp16 X --------
__global__ void gather_kernel(const int* __restrict__ srcidx, const int* __restrict__ off,
                              const int* __restrict__ cnt, const float* __restrict__ TR,
                              const __half* __restrict__ TM, __half* __restrict__ Xh, int Nn) {
    int node = (blockIdx.x * blockDim.x + threadIdx.x) >> 5;
    int lane = threadIdx.x & 31;
    if (node >= Nn) return;

    float s[2][8];
    #pragma unroll
    for (int r = 0; r < 2; r++)
        #pragma unroll
        for (int q = 0; q < 8; q++) s[r][q] = 0.f;

    #pragma unroll
    for (int r = 0; r < 2; r++) {
        const int base = off[node * 2 + r];
        const int n    = cnt[node * 2 + r];
        const size_t coloff = (size_t)r * 256 + lane * 8;
        int e = 0;
        for (; e + 1 < n; e += 2) {
            int s0 = srcidx[base + e], s1 = srcidx[base + e + 1];
            uint4 u0 = *(const uint4*)(TM + (size_t)s0 * 512 + coloff);
            uint4 u1 = *(const uint4*)(TM + (size_t)s1 * 512 + coloff);
            const __half2* h0 = (const __half2*)&u0;
            const __half2* h1 = (const __half2*)&u1;
            #pragma unroll
            for (int q = 0; q < 4; q++) {
                float2 a = __half22float2(h0[q]);
                float2 b = __half22float2(h1[q]);
                s[r][q * 2]     += a.x + b.x;
                s[r][q * 2 + 1] += a.y + b.y;
            }
        }
        if (e < n) {
            int s0 = srcidx[base + e];
            uint4 u0 = *(const uint4*)(TM + (size_t)s0 * 512 + coloff);
            const __half2* h0 = (const __half2*)&u0;
            #pragma unroll
            for (int q = 0; q < 4; q++) {
                float2 a = __half22float2(h0[q]);
                s[r][q * 2]     += a.x;
                s[r][q * 2 + 1] += a.y;
            }
        }
    }
    int c0 = cnt[node * 2], c1 = cnt[node * 2 + 1];
    float inv0 = 1.0f / (float)(c0 > 1 ? c0 : 1);
    float inv1 = 1.0f / (float)(c1 > 1 ? c1 : 1);
    const float4* tr = (const float4*)(TR + (size_t)node * 256) + lane * 2;
    float4 t0 = tr[0], t1 = tr[1];
    __half2 o[4];
    o[0] = __floats2half2_rn(t0.x + s[0][0] * inv0 + s[1][0] * inv1,
                             t0.y + s[0][1] * inv0 + s[1][1] * inv1);
    o[1] = __floats2half2_rn(t0.z + s[0][2] * inv0 + s[1][2] * inv1,
                             t0.w + s[0][3] * inv0 + s[1][3] * inv1);
    o[2] = __floats2half2_rn(t1.x + s[0][4] * inv0 + s[1][4] * inv1,
                             t1.y + s[0][5] * inv0 + s[1][5] * inv1);
    o[3] = __floats2half2_rn(t1.z + s[0][6] * inv0 + s[1][6] * inv1,
                             t1.w + s[0][7] * inv0 + s[1][7] * inv1);
    *(uint4*)(Xh + (size_t)node * 256 + lane * 8) = *(uint4*)o;
}

// ---------------- head --------------------------------------------------------
__global__ void head_kernel(const float* __restrict__ H, const float* __restrict__ W,
                            const float* __restrict__ b, float* __restrict__ out, int Nn) {
    int w = (blockIdx.x * blockDim.x + threadIdx.x) >> 5;
    int lane = threadIdx.x & 31;
    if (w >= Nn) return;
    const float4* h = (const float4*)(H + (long long)w * DHID);
    float d0 = 0.f, d1 = 0.f;
    #pragma unroll
    for (int q = 0; q < 2; q++) {
        float4 hv = h[lane * 2 + q];
        int kbase = lane * 8 + q * 4;
        float4 w01 = ((const float4*)W)[kbase / 2];
        float4 w23 = ((const float4*)W)[kbase / 2 + 1];
        d0 += hv.x * w01.x + hv.y * w01.z + hv.z * w23.x + hv.w * w23.z;
        d1 += hv.x * w01.y + hv.y * w01.w + hv.z * w23.y + hv.w * w23.w;
    }
    #pragma unroll
    for (int off = 16; off > 0; off >>= 1) {
        d0 += __shfl_xor_sync(0xffffffffu, d0, off);
        d1 += __shfl_xor_sync(0xffffffffu, d1, off);
    }
    if (lane == 0) {
        d0 += b[0]; d1 += b[1];
        float m = fmaxf(d0, d1);
        float e0 = expf(d0 - m), e1 = expf(d1 - m);
        float s = e0 + e1;
        out[(long long)w * 2]     = e0 / s;
        out[(long long)w * 2 + 1] = e1 / s;
    }
}

// ---------------- launch ------------------------------------------------------
extern "C" void kernel_launch(void* const* d_in, const int* in_sizes, int n_in,
                              void* d_out, int out_size) {
    const float* x     = (const float*)d_in[0];
    const void*  ei    = d_in[1];
    const void*  et    = d_in[3];
    const float* fc1_W = (const float*)d_in[4];
    const float* fc1_b = (const float*)d_in[5];
    const float* r1_w  = (const float*)d_in[6];
    const float* r1_rt = (const float*)d_in[7];
    const float* r1_b  = (const float*)d_in[8];
    const float* r2_w  = (const float*)d_in[9];
    const float* r2_rt = (const float*)d_in[10];
    const float* r2_b  = (const float*)d_in[11];
    const float* fc2_W = (const float*)d_in[12];
    const float* fc2_b = (const float*)d_in[13];
    const float* out_W = (const float*)d_in[14];
    const float* out_b = (const float*)d_in[15];

    int Nn = in_sizes[0] / DIN;   // 50000
    int E  = in_sizes[3];         // 800000

    float *H1buf, *T, *Xbuf, *F, *RWf;
    int *CNT, *OFF, *CUR, *SRC, *TOT;
    cudaGetSymbolAddress((void**)&H1buf, g_H1);
    cudaGetSymbolAddress((void**)&T,     g_T);
    cudaGetSymbolAddress((void**)&Xbuf,  g_X);
    cudaGetSymbolAddress((void**)&F,     g_F);
    cudaGetSymbolAddress((void**)&RWf,   g_RW);
    cudaGetSymbolAddress((void**)&CNT,   g_CNT);
    cudaGetSymbolAddress((void**)&OFF,   g_OFF);
    cudaGetSymbolAddress((void**)&CUR,   g_CUR);
    cudaGetSymbolAddress((void**)&SRC,   g_SRC);
    cudaGetSymbolAddress((void**)&TOT,   g_TOTAL);

    __half* RW  = (__half*)RWf;
    __half* XH  = (__half*)H1buf;                          // rounded x [N,768]
    __half* H1f = XH + (size_t)MAXN * 768;                 // fc1 out [N,768]
    float*  TR  = T;                                       // root fp32 [N,256]
    __half* TM  = (__half*)(T + (size_t)MAXN * 256);       // msgs [N,512]
    __half* Xh  = (__half*)Xbuf;                           // layer out [N,256]

    cudaFuncSetAttribute(gemm_f16_kernel<2, 1>, cudaFuncAttributeMaxDynamicSharedMemorySize, GEMM_SMEM);
    cudaFuncSetAttribute(gemm_f16_kernel<1, 0>, cudaFuncAttributeMaxDynamicSharedMemorySize, GEMM_SMEM);
    cudaFuncSetAttribute(gemm_f16_kernel<0, 1>, cudaFuncAttributeMaxDynamicSharedMemorySize, GEMM_SMEM);
    cudaFuncSetAttribute(gemm_f16_kernel<2, 0>, cudaFuncAttributeMaxDynamicSharedMemorySize, GEMM_SMEM);

    const int*       ei32 = (const int*)ei;
    const long long* ei64 = (const long long*)ei;
    const int*       et32 = (const int*)et;
    const long long* et64 = (const long long*)et;

    int NC = Nn * NREL;   // 100000
    int mb = (Nn + 127) / 128;            // 391
    long long x4 = (long long)Nn * DIN / 4;

    // Launch order: 6th launch (ncu -s 5 -c 1) = fc1 GEMM.
    probe_kernel<<<1, 32>>>(ei64, (long long)Nn);
    zero_i_kernel<<<(NC + 255) / 256, 256>>>(CNT, NC);
    f2h_kernel<<<(unsigned)((x4 + 255) / 256), 256>>>((const float4*)x, (uint2*)XH, x4);
    f2h_kernel<<<(589824 / 4 + 255) / 256, 256>>>((const float4*)fc1_W, (uint2*)(RW + OFF_FC1), 589824 / 4);
    count_kernel<<<(E + 255) / 256, 256>>>(ei32, ei64, et32, et64, CNT, E);

    // ---- fc1: H1f = half(leaky(XH @ fc1_W + b)) ----  (launch #6 — profiled)
    gemm_f16_kernel<2, 1><<<dim3(mb, 3), 256, GEMM_SMEM>>>(XH, RW + OFF_FC1, H1f, fc1_b, Nn, DIN, DIN, DIN);

    // ---- rest of CSR build + weight conversion ----
    scan_kernel<<<(NC + 255) / 256, 256>>>(CNT, OFF, TOT, NC);
    copy_i_kernel<<<(NC + 255) / 256, 256>>>(OFF, CUR, NC);
    fill_kernel<<<(E + 255) / 256, 256>>>(ei32, ei64, et32, et64, CUR, SRC, E);
    f2h_kernel<<<(196608 / 4 + 255) / 256, 256>>>((const float4*)r1_rt, (uint2*)(RW + OFF_WR1), 196608 / 4);
    f2h_block512_kernel<<<(49152 + 255) / 256, 256>>>((const float4*)r1_w,                (uint2*)(RW + OFF_WM1), 49152, 0);
    f2h_block512_kernel<<<(49152 + 255) / 256, 256>>>((const float4*)(r1_w + DIN * DHID), (uint2*)(RW + OFF_WM1), 49152, 64);
    f2h_kernel<<<(65536 / 4 + 255) / 256, 256>>>((const float4*)r2_rt, (uint2*)(RW + OFF_WR2), 65536 / 4);
    f2h_block512_kernel<<<(16384 + 255) / 256, 256>>>((const float4*)r2_w,                 (uint2*)(RW + OFF_WM2), 16384, 0);
    f2h_block512_kernel<<<(16384 + 255) / 256, 256>>>((const float4*)(r2_w + DHID * DHID), (uint2*)(RW + OFF_WM2), 16384, 64);
    f2h_kernel<<<(65536 / 4 + 255) / 256, 256>>>((const float4*)fc2_W, (uint2*)(RW + OFF_FC2), 65536 / 4);

    // ---- layer-1: root fp32 (+bias) and fp16 messages; A = H1f ----
    gemm_f16_kernel<1, 0><<<dim3(mb, 1), 256, GEMM_SMEM>>>(H1f, RW + OFF_WR1, TR, r1_b, Nn, DIN, DHID, DHID);
    gemm_f16_kernel<0, 1><<<dim3(mb, 2), 256, GEMM_SMEM>>>(H1f, RW + OFF_WM1, TM, nullptr, Nn, DIN, 512, 512);
    gather_kernel<<<(Nn + 7) / 8, 256>>>(SRC, OFF, CNT, TR, TM, Xh, Nn);

    // ---- layer-2: A = Xh ----
    gemm_f16_kernel<1, 0><<<dim3(mb, 1), 256, GEMM_SMEM>>>(Xh, RW + OFF_WR2, TR, r2_b, Nn, DHID, DHID, DHID);
    gemm_f16_kernel<0, 1><<<dim3(mb, 2), 256, GEMM_SMEM>>>(Xh, RW + OFF_WM2, TM, nullptr, Nn, DHID, 512, 512);
    gather_kernel<<<(Nn + 7) / 8, 256>>>(SRC, OFF, CNT, TR, TM, Xh, Nn);

    // ---- fc2: F = leaky(Xh @ fc2_W + b), fp32 out ----
    gemm_f16_kernel<2, 0><<<dim3(mb, 1), 256, GEMM_SMEM>>>(Xh, RW + OFF_FC2, F, fc2_b, Nn, DHID, DHID, DHID);

    // ---- head + softmax ----
    head_kernel<<<(Nn + 7) / 8, 256>>>(F, out_W, out_b, (float*)d_out, Nn);
}

// round 16
// speedup vs baseline: 1.4587x; 1.4587x over previous
#include <cuda_runtime.h>
#include <cuda_fp16.h>
#include <cstdint>
#include <math.h>

#define DIN  768
#define DHID 256
#define NREL 2
#define MAXN 50000
#define MAXE 800000

// ---------------- scratch (device globals) ------------------------------------
__device__ float g_H1[(size_t)MAXN * DIN];    // halves: XH [N,768] | H1f [N,768]
__device__ float g_T [(size_t)MAXN * 768];    // TR fp32 [N,256] + TM half [N,512]
__device__ float g_X [(size_t)MAXN * DHID];   // Xh half [N,256]
__device__ float g_F [(size_t)MAXN * DHID];   // fc2 output fp32 [N,256]
__device__ float g_RW[1441792];               // fp16 weights (as half storage)
__device__ int   g_CNT[MAXN * NREL];
__device__ int   g_OFF[MAXN * NREL];
__device__ int   g_CUR[MAXN * NREL];
__device__ int   g_SRC[MAXE];
__device__ int   g_TOTAL[1];
__device__ int   g_flag[1];

// offsets into weight buffer (halves)
#define OFF_FC1   0           // [768x768]
#define OFF_WR1   589824      // [768x256]
#define OFF_WM1   786432      // [768x512]
#define OFF_WR2   1179648     // [256x256]
#define OFF_WM2   1245184     // [256x512]
#define OFF_FC2   1376256     // [256x256]

// ---------------- helpers ------------------------------------------------------
__device__ __forceinline__ void mma16816(float* c, const uint32_t* a, const uint32_t* b) {
    asm volatile("mma.sync.aligned.m16n8k16.row.col.f32.f16.f16.f32 "
                 "{%0,%1,%2,%3}, {%4,%5,%6,%7}, {%8,%9}, {%0,%1,%2,%3};"
                 : "+f"(c[0]), "+f"(c[1]), "+f"(c[2]), "+f"(c[3])
                 : "r"(a[0]), "r"(a[1]), "r"(a[2]), "r"(a[3]), "r"(b[0]), "r"(b[1]));
}
__device__ __forceinline__ void cpasync16(uint32_t saddr, const void* gptr, uint32_t sz) {
    asm volatile("cp.async.ca.shared.global [%0], [%1], 16, %2;"
                 :: "r"(saddr), "l"(gptr), "r"(sz) : "memory");
}
__device__ __forceinline__ uint32_t smem_u32(const void* p) {
    uint32_t a;
    asm("{ .reg .u64 t; cvta.to.shared.u64 t, %1; cvt.u32.u64 %0, t; }" : "=r"(a) : "l"(p));
    return a;
}

// ---------------- fp16 mma.sync GEMM: 128x256 block, 64x64 warp tile -----------
// BK=32 halves. cp.async 4-stage ring; ldmatrix.x4 A, ldmatrix.x4.trans B.
// EPI: 0 none, 1 +bias, 2 +bias+leaky. OUTH: 1 = half output, 0 = fp32.
#define APADH 40      // A row stride in halves (32 + 8) -> 80B
#define BPADH 264     // B row stride in halves (256 + 8) -> 528B
#define BN    256
#define STAGES 4
#define ASZH (128 * APADH)          // halves
#define BSZH (32 * BPADH)
#define GEMM_SMEM (STAGES * (ASZH + BSZH) * 2)

template<int EPI, int OUTH>
__global__ void __launch_bounds__(256, 1)
gemm_f16_kernel(const __half* __restrict__ A, const __half* __restrict__ B,
                void* __restrict__ Cv, const float* __restrict__ bias,
                int M, int K, int ldb, int ldc) {
    extern __shared__ __half smh[];
    const uint32_t smem_base = smem_u32(smh);

    const int tid  = threadIdx.x;
    const int w    = tid >> 5;
    const int lane = tid & 31;
    const int g    = lane >> 2;
    const int cq   = lane & 3;
    const int wm   = w >> 2;      // 0..1
    const int wn   = w & 3;       // 0..3
    const int row0 = blockIdx.x * 128;
    const int col0 = blockIdx.y * BN;

    // A fill: 128 rows x 64B = 512 x 16B chunks, 2/thread
    const int ar  = tid >> 2;
    const int ac16 = tid & 3;
    const uint32_t aoff0 = (uint32_t)(ar * 80 + ac16 * 16);
    const uint32_t aoff1 = aoff0 + 64u * 80u;
    const int gr0 = row0 + ar, gr1 = row0 + ar + 64;
    const uint32_t sz0 = (gr0 < M) ? 16u : 0u;
    const uint32_t sz1 = (gr1 < M) ? 16u : 0u;
    const __half* agp0 = A + (size_t)(gr0 < M ? gr0 : 0) * K + ac16 * 8;
    const __half* agp1 = A + (size_t)(gr1 < M ? gr1 : 0) * K + ac16 * 8;

    // B fill: 32 rows x 512B = 1024 x 16B chunks, 4/thread
    uint32_t boff[4];
    const __half* bgp[4];
    #pragma unroll
    for (int it = 0; it < 4; it++) {
        int idx = tid + it * 256;
        int brow = idx >> 5, bc16 = idx & 31;
        boff[it] = (uint32_t)(brow * 528 + bc16 * 16);
        bgp[it]  = B + (size_t)brow * ldb + col0 + bc16 * 8;
    }
    const size_t bstep = (size_t)32 * ldb;

    // ldmatrix A lane mapping (x4: m0 r0-7 k0-7 | m1 r8-15 k0-7 | m2 r0-7 k8-15 | m3 r8-15 k8-15)
    const int lm_mat  = lane >> 3;
    const int lm_row  = (lane & 7) + ((lm_mat & 1) << 3);
    const int lm_koff = (lm_mat >> 1) * 8;                      // halves
    const uint32_t a_lm_off = (uint32_t)(((wm * 64 + lm_row) * APADH + lm_koff) * 2);

    // ldmatrix B trans lane mapping (m0 k0-7@n0 | m1 k8-15@n0 | m2 k0-7@n8 | m3 k8-15@n8)
    const int b_krow = ((lm_mat & 1) << 3) + (lane & 7);
    const int b_coff = (lm_mat >> 1) * 8;                        // halves
    const uint32_t b_lm_base = (uint32_t)((b_krow * BPADH + wn * 64 + b_coff) * 2);

    const int nk = K >> 5;   // K/32

    auto issue_stage = [&](int s, int t) {
        uint32_t abase = smem_base + (uint32_t)(s * ASZH) * 2;
        uint32_t bbase = smem_base + (uint32_t)(STAGES * ASZH + s * BSZH) * 2;
        cpasync16(abase + aoff0, agp0 + t * 32, sz0);
        cpasync16(abase + aoff1, agp1 + t * 32, sz1);
        #pragma unroll
        for (int it = 0; it < 4; it++)
            cpasync16(bbase + boff[it], bgp[it] + (size_t)t * bstep, 16u);
        asm volatile("cp.async.commit_group;" ::: "memory");
    };

    float acc[4][8][4];
    #pragma unroll
    for (int mi = 0; mi < 4; mi++)
        #pragma unroll
        for (int ni = 0; ni < 8; ni++)
            #pragma unroll
            for (int q = 0; q < 4; q++) acc[mi][ni][q] = 0.f;

    issue_stage(0, 0);
    if (nk > 1) issue_stage(1, 1); else asm volatile("cp.async.commit_group;" ::: "memory");
    if (nk > 2) issue_stage(2, 2); else asm volatile("cp.async.commit_group;" ::: "memory");

    for (int t = 0; t < nk; t++) {
        if (t + 2 < nk)      { asm volatile("cp.async.wait_group 2;" ::: "memory"); }
        else if (t + 1 < nk) { asm volatile("cp.async.wait_group 1;" ::: "memory"); }
        else                 { asm volatile("cp.async.wait_group 0;" ::: "memory"); }
        __syncthreads();
        if (t + 3 < nk) issue_stage((t + 3) % STAGES, t + 3);

        const int s = t % STAGES;
        const uint32_t aS = smem_base + (uint32_t)(s * ASZH) * 2;
        const uint32_t bS = smem_base + (uint32_t)(STAGES * ASZH + s * BSZH) * 2;

        #pragma unroll
        for (int k16 = 0; k16 < 2; k16++) {
            uint32_t af[4][4];
            #pragma unroll
            for (int mi = 0; mi < 4; mi++) {
                uint32_t addr = aS + a_lm_off + (uint32_t)((mi * 16 * APADH + k16 * 16) * 2);
                asm volatile("ldmatrix.sync.aligned.m8n8.x4.shared.b16 {%0,%1,%2,%3}, [%4];"
                    : "=r"(af[mi][0]), "=r"(af[mi][1]), "=r"(af[mi][2]), "=r"(af[mi][3])
                    : "r"(addr));
            }
            uint32_t bf[8][2];
            #pragma unroll
            for (int p = 0; p < 4; p++) {
                uint32_t addr = bS + b_lm_base + (uint32_t)((k16 * 16 * BPADH + p * 16) * 2);
                asm volatile("ldmatrix.sync.aligned.m8n8.x4.trans.shared.b16 {%0,%1,%2,%3}, [%4];"
                    : "=r"(bf[2 * p][0]), "=r"(bf[2 * p][1]),
                      "=r"(bf[2 * p + 1][0]), "=r"(bf[2 * p + 1][1])
                    : "r"(addr));
            }
            #pragma unroll
            for (int mi = 0; mi < 4; mi++)
                #pragma unroll
                for (int ni = 0; ni < 8; ni++)
                    mma16816(acc[mi][ni], af[mi], bf[ni]);
        }
        // no trailing barrier: top barrier of next iter orders buffer reuse
    }

    #pragma unroll
    for (int mi = 0; mi < 4; mi++) {
        int rbase = row0 + wm * 64 + mi * 16;
        int r0 = rbase + g, r1 = rbase + g + 8;
        #pragma unroll
        for (int ni = 0; ni < 8; ni++) {
            int col = col0 + wn * 64 + ni * 8 + cq * 2;
            float b0 = 0.f, b1 = 0.f;
            if (EPI >= 1) { b0 = bias[col]; b1 = bias[col + 1]; }
            float v0 = acc[mi][ni][0] + b0, v1 = acc[mi][ni][1] + b1;
            float v2 = acc[mi][ni][2] + b0, v3 = acc[mi][ni][3] + b1;
            if (EPI == 2) {
                v0 = v0 >= 0.f ? v0 : 0.01f * v0;
                v1 = v1 >= 0.f ? v1 : 0.01f * v1;
                v2 = v2 >= 0.f ? v2 : 0.01f * v2;
                v3 = v3 >= 0.f ? v3 : 0.01f * v3;
            }
            if (OUTH) {
                __half* Ch = (__half*)Cv;
                if (r0 < M) *(__half2*)(Ch + (size_t)r0 * ldc + col) = __floats2half2_rn(v0, v1);
                if (r1 < M) *(__half2*)(Ch + (size_t)r1 * ldc + col) = __floats2half2_rn(v2, v3);
            } else {
                float* C = (float*)Cv;
                if (r0 < M) *(float2*)(C + (size_t)r0 * ldc + col) = make_float2(v0, v1);
                if (r1 < M) *(float2*)(C + (size_t)r1 * ldc + col) = make_float2(v2, v3);
            }
        }
    }
}

// ---------------- fp32 -> fp16 conversion kernels ------------------------------
__global__ void f2h_kernel(const float4* __restrict__ src, uint2* __restrict__ dst,
                           long long n4) {
    long long i = (long long)blockIdx.x * blockDim.x + threadIdx.x;
    if (i < n4) {
        float4 v = src[i];
        __half2 h0 = __floats2half2_rn(v.x, v.y);
        __half2 h1 = __floats2half2_rn(v.z, v.w);
        dst[i] = make_uint2(*(uint32_t*)&h0, *(uint32_t*)&h1);
    }
}
// [K x 256] fp32 -> half into 512-wide buffer at column block (dst uint2 units)
__global__ void f2h_block512_kernel(const float4* __restrict__ src, uint2* __restrict__ dst,
                                    int n4, int cb4) {   // n4 = K*64, cb4 = colblock/4
    int i = blockIdx.x * blockDim.x + threadIdx.x;
    if (i >= n4) return;
    int row = i >> 6, c = i & 63;
    float4 v = src[i];
    __half2 h0 = __floats2half2_rn(v.x, v.y);
    __half2 h1 = __floats2half2_rn(v.z, v.w);
    dst[row * 128 + cb4 + c] = make_uint2(*(uint32_t*)&h0, *(uint32_t*)&h1);
}

// ---------------- edge machinery ----------------------------------------------
__global__ void probe_kernel(const long long* __restrict__ ei, long long Nn) {
    if (blockIdx.x == 0 && threadIdx.x == 0) {
        int ok = 1;
        for (int i = 0; i < 16; i++) {
            long long v = ei[i];
            if (v < 0 || v >= Nn) ok = 0;
        }
        g_flag[0] = ok;
        g_TOTAL[0] = 0;
    }
}
__global__ void zero_i_kernel(int* __restrict__ p, int n) {
    int i = blockIdx.x * blockDim.x + threadIdx.x;
    if (i < n) p[i] = 0;
}
__global__ void count_kernel(const int* __restrict__ ei32, const long long* __restrict__ ei64,
                             const int* __restrict__ et32, const long long* __restrict__ et64,
                             int* __restrict__ cnt, int E) {
    int e = blockIdx.x * blockDim.x + threadIdx.x;
    if (e >= E) return;
    long long dst; int r;
    if (g_flag[0]) { dst = ei64[(long long)E + e]; r = (int)et64[e]; }
    else           { dst = ei32[E + e];            r = et32[e]; }
    atomicAdd(&cnt[(int)dst * NREL + r], 1);
}
__global__ void scan_kernel(const int* __restrict__ cnt, int* __restrict__ off,
                            int* __restrict__ total, int n) {
    __shared__ int sh[256];
    __shared__ int base_sh;
    int i = blockIdx.x * 256 + threadIdx.x;
    int v = (i < n) ? cnt[i] : 0;
    sh[threadIdx.x] = v;
    __syncthreads();
    #pragma unroll
    for (int d = 1; d < 256; d <<= 1) {
        int t = (threadIdx.x >= d) ? sh[threadIdx.x - d] : 0;
        __syncthreads();
        sh[threadIdx.x] += t;
        __syncthreads();
    }
    if (threadIdx.x == 255) base_sh = atomicAdd(total, sh[255]);
    __syncthreads();
    if (i < n) off[i] = base_sh + sh[threadIdx.x] - v;
}
__global__ void copy_i_kernel(const int* __restrict__ s, int* __restrict__ d, int n) {
    int i = blockIdx.x * blockDim.x + threadIdx.x;
    if (i < n) d[i] = s[i];
}
__global__ void fill_kernel(const int* __restrict__ ei32, const long long* __restrict__ ei64,
                            const int* __restrict__ et32, const long long* __restrict__ et64,
                            int* __restrict__ cur, int* __restrict__ srcidx, int E) {
    int e = blockIdx.x * blockDim.x + threadIdx.x;
    if (e >= E) return;
    long long src, dst; int r;
    if (g_flag[0]) { src = ei64[e]; dst = ei64[(long long)E + e]; r = (int)et64[e]; }
    else           { src = ei32[e]; dst = ei32[E + e];            r = et32[e]; }
    int p = atomicAdd(&cur[(int)dst * NREL + r], 1);
    srcidx[p] = (int)src;
}

// ---------------- fused gather (fp16 msgs, MLP=4) + mean + fp32 root -> fp16 X --
__global__ void gather_kernel(const int* __restrict__ srcidx, const int* __restrict__ off,
                              const int* __restrict__ cnt, const float* __restrict__ TR,
                              const __half* __restrict__ TM, __half* __restrict__ Xh, int Nn) {
    int node = (blockIdx.x * blockDim.x + threadIdx.x) >> 5;
    int lane = threadIdx.x & 31;
    if (node >= Nn) return;

    float s[2][8];
    #pragma unroll
    for (int r = 0; r < 2; r++)
        #pragma unroll
        for (int q = 0; q < 8; q++) s[r][q] = 0.f;

    #pragma unroll
    for (int r = 0; r < 2; r++) {
        const int base = off[node * 2 + r];
        const int n    = cnt[node * 2 + r];
        const size_t coloff = (size_t)r * 256 + lane * 8;
        int e = 0;
        for (; e + 3 < n; e += 4) {
            int i0 = srcidx[base + e],     i1 = srcidx[base + e + 1];
            int i2 = srcidx[base + e + 2], i3 = srcidx[base + e + 3];
            uint4 u0 = *(const uint4*)(TM + (size_t)i0 * 512 + coloff);
            uint4 u1 = *(const uint4*)(TM + (size_t)i1 * 512 + coloff);
            uint4 u2 = *(const uint4*)(TM + (size_t)i2 * 512 + coloff);
            uint4 u3 = *(const uint4*)(TM + (size_t)i3 * 512 + coloff);
            const __half2* h0 = (const __half2*)&u0;
            const __half2* h1 = (const __half2*)&u1;
            const __half2* h2 = (const __half2*)&u2;
            const __half2* h3 = (const __half2*)&u3;
            #pragma unroll
            for (int q = 0; q < 4; q++) {
                float2 a = __half22float2(h0[q]);
                float2 b = __half22float2(h1[q]);
                float2 c = __half22float2(h2[q]);
                float2 d = __half22float2(h3[q]);
                s[r][q * 2]     += (a.x + b.x) + (c.x + d.x);
                s[r][q * 2 + 1] += (a.y + b.y) + (c.y + d.y);
            }
        }
        for (; e < n; e++) {
            int i0 = srcidx[base + e];
            uint4 u0 = *(const uint4*)(TM + (size_t)i0 * 512 + coloff);
            const __half2* h0 = (const __half2*)&u0;
            #pragma unroll
            for (int q = 0; q < 4; q++) {
                float2 a = __half22float2(h0[q]);
                s[r][q * 2]     += a.x;
                s[r][q * 2 + 1] += a.y;
            }
        }
    }
    int c0 = cnt[node * 2], c1 = cnt[node * 2 + 1];
    float inv0 = 1.0f / (float)(c0 > 1 ? c0 : 1);
    float inv1 = 1.0f / (float)(c1 > 1 ? c1 : 1);
    const float4* tr = (const float4*)(TR + (size_t)node * 256) + lane * 2;
    float4 t0 = tr[0], t1 = tr[1];
    __half2 o[4];
    o[0] = __floats2half2_rn(t0.x + s[0][0] * inv0 + s[1][0] * inv1,
                             t0.y + s[0][1] * inv0 + s[1][1] * inv1);
    o[1] = __floats2half2_rn(t0.z + s[0][2] * inv0 + s[1][2] * inv1,
                             t0.w + s[0][3] * inv0 + s[1][3] * inv1);
    o[2] = __floats2half2_rn(t1.x + s[0][4] * inv0 + s[1][4] * inv1,
                             t1.y + s[0][5] * inv0 + s[1][5] * inv1);
    o[3] = __floats2half2_rn(t1.z + s[0][6] * inv0 + s[1][6] * inv1,
                             t1.w + s[0][7] * inv0 + s[1][7] * inv1);
    *(uint4*)(Xh + (size_t)node * 256 + lane * 8) = *(uint4*)o;
}

// ---------------- head --------------------------------------------------------
__global__ void head_kernel(const float* __restrict__ H, const float* __restrict__ W,
                            const float* __restrict__ b, float* __restrict__ out, int Nn) {
    int w = (blockIdx.x * blockDim.x + threadIdx.x) >> 5;
    int lane = threadIdx.x & 31;
    if (w >= Nn) return;
    const float4* h = (const float4*)(H + (long long)w * DHID);
    float d0 = 0.f, d1 = 0.f;
    #pragma unroll
    for (int q = 0; q < 2; q++) {
        float4 hv = h[lane * 2 + q];
        int kbase = lane * 8 + q * 4;
        float4 w01 = ((const float4*)W)[kbase / 2];
        float4 w23 = ((const float4*)W)[kbase / 2 + 1];
        d0 += hv.x * w01.x + hv.y * w01.z + hv.z * w23.x + hv.w * w23.z;
        d1 += hv.x * w01.y + hv.y * w01.w + hv.z * w23.y + hv.w * w23.w;
    }
    #pragma unroll
    for (int off = 16; off > 0; off >>= 1) {
        d0 += __shfl_xor_sync(0xffffffffu, d0, off);
        d1 += __shfl_xor_sync(0xffffffffu, d1, off);
    }
    if (lane == 0) {
        d0 += b[0]; d1 += b[1];
        float m = fmaxf(d0, d1);
        float e0 = expf(d0 - m), e1 = expf(d1 - m);
        float s = e0 + e1;
        out[(long long)w * 2]     = e0 / s;
        out[(long long)w * 2 + 1] = e1 / s;
    }
}

// ---------------- launch ------------------------------------------------------
extern "C" void kernel_launch(void* const* d_in, const int* in_sizes, int n_in,
                              void* d_out, int out_size) {
    const float* x     = (const float*)d_in[0];
    const void*  ei    = d_in[1];
    const void*  et    = d_in[3];
    const float* fc1_W = (const float*)d_in[4];
    const float* fc1_b = (const float*)d_in[5];
    const float* r1_w  = (const float*)d_in[6];
    const float* r1_rt = (const float*)d_in[7];
    const float* r1_b  = (const float*)d_in[8];
    const float* r2_w  = (const float*)d_in[9];
    const float* r2_rt = (const float*)d_in[10];
    const float* r2_b  = (const float*)d_in[11];
    const float* fc2_W = (const float*)d_in[12];
    const float* fc2_b = (const float*)d_in[13];
    const float* out_W = (const float*)d_in[14];
    const float* out_b = (const float*)d_in[15];

    int Nn = in_sizes[0] / DIN;   // 50000
    int E  = in_sizes[3];         // 800000

    float *H1buf, *T, *Xbuf, *F, *RWf;
    int *CNT, *OFF, *CUR, *SRC, *TOT;
    cudaGetSymbolAddress((void**)&H1buf, g_H1);
    cudaGetSymbolAddress((void**)&T,     g_T);
    cudaGetSymbolAddress((void**)&Xbuf,  g_X);
    cudaGetSymbolAddress((void**)&F,     g_F);
    cudaGetSymbolAddress((void**)&RWf,   g_RW);
    cudaGetSymbolAddress((void**)&CNT,   g_CNT);
    cudaGetSymbolAddress((void**)&OFF,   g_OFF);
    cudaGetSymbolAddress((void**)&CUR,   g_CUR);
    cudaGetSymbolAddress((void**)&SRC,   g_SRC);
    cudaGetSymbolAddress((void**)&TOT,   g_TOTAL);

    __half* RW  = (__half*)RWf;
    __half* XH  = (__half*)H1buf;                          // rounded x [N,768]
    __half* H1f = XH + (size_t)MAXN * 768;                 // fc1 out [N,768]
    float*  TR  = T;                                       // root fp32 [N,256]
    __half* TM  = (__half*)(T + (size_t)MAXN * 256);       // msgs [N,512]
    __half* Xh  = (__half*)Xbuf;                           // layer out [N,256]

    cudaFuncSetAttribute(gemm_f16_kernel<2, 1>, cudaFuncAttributeMaxDynamicSharedMemorySize, GEMM_SMEM);
    cudaFuncSetAttribute(gemm_f16_kernel<1, 0>, cudaFuncAttributeMaxDynamicSharedMemorySize, GEMM_SMEM);
    cudaFuncSetAttribute(gemm_f16_kernel<0, 1>, cudaFuncAttributeMaxDynamicSharedMemorySize, GEMM_SMEM);
    cudaFuncSetAttribute(gemm_f16_kernel<2, 0>, cudaFuncAttributeMaxDynamicSharedMemorySize, GEMM_SMEM);

    const int*       ei32 = (const int*)ei;
    const long long* ei64 = (const long long*)ei;
    const int*       et32 = (const int*)et;
    const long long* et64 = (const long long*)et;

    int NC = Nn * NREL;   // 100000
    int mb = (Nn + 127) / 128;            // 391
    long long x4 = (long long)Nn * DIN / 4;

    // Launch order: 6th launch (ncu -s 5 -c 1) = fc1 GEMM.
    probe_kernel<<<1, 32>>>(ei64, (long long)Nn);
    zero_i_kernel<<<(NC + 255) / 256, 256>>>(CNT, NC);
    f2h_kernel<<<(unsigned)((x4 + 255) / 256), 256>>>((const float4*)x, (uint2*)XH, x4);
    f2h_kernel<<<(589824 / 4 + 255) / 256, 256>>>((const float4*)fc1_W, (uint2*)(RW + OFF_FC1), 589824 / 4);
    count_kernel<<<(E + 255) / 256, 256>>>(ei32, ei64, et32, et64, CNT, E);

    // ---- fc1: H1f = half(leaky(XH @ fc1_W + b)) ----  (launch #6 — profiled)
    gemm_f16_kernel<2, 1><<<dim3(mb, 3), 256, GEMM_SMEM>>>(XH, RW + OFF_FC1, H1f, fc1_b, Nn, DIN, DIN, DIN);

    // ---- rest of CSR build + weight conversion ----
    scan_kernel<<<(NC + 255) / 256, 256>>>(CNT, OFF, TOT, NC);
    copy_i_kernel<<<(NC + 255) / 256, 256>>>(OFF, CUR, NC);
    fill_kernel<<<(E + 255) / 256, 256>>>(ei32, ei64, et32, et64, CUR, SRC, E);
    f2h_kernel<<<(196608 / 4 + 255) / 256, 256>>>((const float4*)r1_rt, (uint2*)(RW + OFF_WR1), 196608 / 4);
    f2h_block512_kernel<<<(49152 + 255) / 256, 256>>>((const float4*)r1_w,                (uint2*)(RW + OFF_WM1), 49152, 0);
    f2h_block512_kernel<<<(49152 + 255) / 256, 256>>>((const float4*)(r1_w + DIN * DHID), (uint2*)(RW + OFF_WM1), 49152, 64);
    f2h_kernel<<<(65536 / 4 + 255) / 256, 256>>>((const float4*)r2_rt, (uint2*)(RW + OFF_WR2), 65536 / 4);
    f2h_block512_kernel<<<(16384 + 255) / 256, 256>>>((const float4*)r2_w,                 (uint2*)(RW + OFF_WM2), 16384, 0);
    f2h_block512_kernel<<<(16384 + 255) / 256, 256>>>((const float4*)(r2_w + DHID * DHID), (uint2*)(RW + OFF_WM2), 16384, 64);
    f2h_kernel<<<(65536 / 4 + 255) / 256, 256>>>((const float4*)fc2_W, (uint2*)(RW + OFF_FC2), 65536 / 4);

    // ---- layer-1: root fp32 (+bias) and fp16 messages; A = H1f ----
    gemm_f16_kernel<1, 0><<<dim3(mb, 1), 256, GEMM_SMEM>>>(H1f, RW + OFF_WR1, TR, r1_b, Nn, DIN, DHID, DHID);
    gemm_f16_kernel<0, 1><<<dim3(mb, 2), 256, GEMM_SMEM>>>(H1f, RW + OFF_WM1, TM, nullptr, Nn, DIN, 512, 512);
    gather_kernel<<<(Nn + 7) / 8, 256>>>(SRC, OFF, CNT, TR, TM, Xh, Nn);

    // ---- layer-2: A = Xh ----
    gemm_f16_kernel<1, 0><<<dim3(mb, 1), 256, GEMM_SMEM>>>(Xh, RW + OFF_WR2, TR, r2_b, Nn, DHID, DHID, DHID);
    gemm_f16_kernel<0, 1><<<dim3(mb, 2), 256, GEMM_SMEM>>>(Xh, RW + OFF_WM2, TM, nullptr, Nn, DHID, 512, 512);
    gather_kernel<<<(Nn + 7) / 8, 256>>>(SRC, OFF, CNT, TR, TM, Xh, Nn);

    // ---- fc2: F = leaky(Xh @ fc2_W + b), fp32 out ----
    gemm_f16_kernel<2, 0><<<dim3(mb, 1), 256, GEMM_SMEM>>>(Xh, RW + OFF_FC2, F, fc2_b, Nn, DHID, DHID, DHID);

    // ---- head + softmax ----
    head_kernel<<<(Nn + 7) / 8, 256>>>(F, out_W, out_b, (float*)d_out, Nn);
}

// round 17
// speedup vs baseline: 2.1138x; 1.4491x over previous
#include <cuda_runtime.h>
#include <cuda_fp16.h>
#include <cstdint>
#include <math.h>

#define DIN  768
#define DHID 256
#define NREL 2
#define MAXN 50000
#define MAXE 800000

// ---------------- scratch (device globals) ------------------------------------
__device__ float g_H1[(size_t)MAXN * DIN];    // halves: XH [N,768] | H1f [N,768]
__device__ float g_T [(size_t)MAXN * 768];    // TR fp32 [N,256] + TM half [N,512]
__device__ float g_X [(size_t)MAXN * DHID];   // Xh half [N,256]
__device__ float g_F [(size_t)MAXN * DHID];   // fc2 output fp32 [N,256]
__device__ float g_RW[1441792];               // fp16 weights (as half storage)
__device__ int   g_CNT[MAXN * NREL];
__device__ int   g_OFF[MAXN * NREL];
__device__ int   g_CUR[MAXN * NREL];
__device__ int   g_SRC[MAXE];
__device__ int   g_TOTAL[1];
__device__ int   g_flag[1];

// offsets into weight buffer (halves)
#define OFF_FC1   0           // [768x768]
#define OFF_WR1   589824      // [768x256]
#define OFF_WM1   786432      // [768x512]
#define OFF_WR2   1179648     // [256x256]
#define OFF_WM2   1245184     // [256x512]
#define OFF_FC2   1376256     // [256x256]

// ---------------- helpers ------------------------------------------------------
__device__ __forceinline__ void mma16816(float* c, const uint32_t* a, const uint32_t* b) {
    asm volatile("mma.sync.aligned.m16n8k16.row.col.f32.f16.f16.f32 "
                 "{%0,%1,%2,%3}, {%4,%5,%6,%7}, {%8,%9}, {%0,%1,%2,%3};"
                 : "+f"(c[0]), "+f"(c[1]), "+f"(c[2]), "+f"(c[3])
                 : "r"(a[0]), "r"(a[1]), "r"(a[2]), "r"(a[3]), "r"(b[0]), "r"(b[1]));
}
__device__ __forceinline__ void cpasync16(uint32_t saddr, const void* gptr, uint32_t sz) {
    asm volatile("cp.async.ca.shared.global [%0], [%1], 16, %2;"
                 :: "r"(saddr), "l"(gptr), "r"(sz) : "memory");
}
__device__ __forceinline__ uint32_t smem_u32(const void* p) {
    uint32_t a;
    asm("{ .reg .u64 t; cvta.to.shared.u64 t, %1; cvt.u32.u64 %0, t; }" : "=r"(a) : "l"(p));
    return a;
}

// ---------------- fp16 mma.sync GEMM: 128x256 block, 64x64 warp tile -----------
// BK=32 halves. cp.async 4-stage ring; ldmatrix.x4 A, ldmatrix.x4.trans B.
// EPI: 0 none, 1 +bias, 2 +bias+leaky. OUTH: 1 = half output, 0 = fp32.
#define APADH 40      // A row stride in halves (32 + 8) -> 80B
#define BPADH 264     // B row stride in halves (256 + 8) -> 528B
#define BN    256
#define STAGES 4
#define ASZH (128 * APADH)          // halves
#define BSZH (32 * BPADH)
#define GEMM_SMEM (STAGES * (ASZH + BSZH) * 2)

template<int EPI, int OUTH>
__global__ void __launch_bounds__(256, 1)
gemm_f16_kernel(const __half* __restrict__ A, const __half* __restrict__ B,
                void* __restrict__ Cv, const float* __restrict__ bias,
                int M, int K, int ldb, int ldc) {
    extern __shared__ __half smh[];
    const uint32_t smem_base = smem_u32(smh);

    const int tid  = threadIdx.x;
    const int w    = tid >> 5;
    const int lane = tid & 31;
    const int g    = lane >> 2;
    const int cq   = lane & 3;
    const int wm   = w >> 2;      // 0..1
    const int wn   = w & 3;       // 0..3
    const int row0 = blockIdx.x * 128;
    const int col0 = blockIdx.y * BN;

    // A fill: 128 rows x 64B = 512 x 16B chunks, 2/thread
    const int ar  = tid >> 2;
    const int ac16 = tid & 3;
    const uint32_t aoff0 = (uint32_t)(ar * 80 + ac16 * 16);
    const uint32_t aoff1 = aoff0 + 64u * 80u;
    const int gr0 = row0 + ar, gr1 = row0 + ar + 64;
    const uint32_t sz0 = (gr0 < M) ? 16u : 0u;
    const uint32_t sz1 = (gr1 < M) ? 16u : 0u;
    const __half* agp0 = A + (size_t)(gr0 < M ? gr0 : 0) * K + ac16 * 8;
    const __half* agp1 = A + (size_t)(gr1 < M ? gr1 : 0) * K + ac16 * 8;

    // B fill: 32 rows x 512B = 1024 x 16B chunks, 4/thread
    uint32_t boff[4];
    const __half* bgp[4];
    #pragma unroll
    for (int it = 0; it < 4; it++) {
        int idx = tid + it * 256;
        int brow = idx >> 5, bc16 = idx & 31;
        boff[it] = (uint32_t)(brow * 528 + bc16 * 16);
        bgp[it]  = B + (size_t)brow * ldb + col0 + bc16 * 8;
    }
    const size_t bstep = (size_t)32 * ldb;

    // ldmatrix A lane mapping (x4: m0 r0-7 k0-7 | m1 r8-15 k0-7 | m2 r0-7 k8-15 | m3 r8-15 k8-15)
    const int lm_mat  = lane >> 3;
    const int lm_row  = (lane & 7) + ((lm_mat & 1) << 3);
    const int lm_koff = (lm_mat >> 1) * 8;                      // halves
    const uint32_t a_lm_off = (uint32_t)(((wm * 64 + lm_row) * APADH + lm_koff) * 2);

    // ldmatrix B trans lane mapping (m0 k0-7@n0 | m1 k8-15@n0 | m2 k0-7@n8 | m3 k8-15@n8)
    const int b_krow = ((lm_mat & 1) << 3) + (lane & 7);
    const int b_coff = (lm_mat >> 1) * 8;                        // halves
    const uint32_t b_lm_base = (uint32_t)((b_krow * BPADH + wn * 64 + b_coff) * 2);

    const int nk = K >> 5;   // K/32

    auto issue_stage = [&](int s, int t) {
        uint32_t abase = smem_base + (uint32_t)(s * ASZH) * 2;
        uint32_t bbase = smem_base + (uint32_t)(STAGES * ASZH + s * BSZH) * 2;
        cpasync16(abase + aoff0, agp0 + t * 32, sz0);
        cpasync16(abase + aoff1, agp1 + t * 32, sz1);
        #pragma unroll
        for (int it = 0; it < 4; it++)
            cpasync16(bbase + boff[it], bgp[it] + (size_t)t * bstep, 16u);
        asm volatile("cp.async.commit_group;" ::: "memory");
    };

    float acc[4][8][4];
    #pragma unroll
    for (int mi = 0; mi < 4; mi++)
        #pragma unroll
        for (int ni = 0; ni < 8; ni++)
            #pragma unroll
            for (int q = 0; q < 4; q++) acc[mi][ni][q] = 0.f;

    issue_stage(0, 0);
    if (nk > 1) issue_stage(1, 1); else asm volatile("cp.async.commit_group;" ::: "memory");
    if (nk > 2) issue_stage(2, 2); else asm volatile("cp.async.commit_group;" ::: "memory");

    for (int t = 0; t < nk; t++) {
        if (t + 2 < nk)      { asm volatile("cp.async.wait_group 2;" ::: "memory"); }
        else if (t + 1 < nk) { asm volatile("cp.async.wait_group 1;" ::: "memory"); }
        else                 { asm volatile("cp.async.wait_group 0;" ::: "memory"); }
        __syncthreads();
        if (t + 3 < nk) issue_stage((t + 3) % STAGES, t + 3);

        const int s = t % STAGES;
        const uint32_t aS = smem_base + (uint32_t)(s * ASZH) * 2;
        const uint32_t bS = smem_base + (uint32_t)(STAGES * ASZH + s * BSZH) * 2;

        #pragma unroll
        for (int k16 = 0; k16 < 2; k16++) {
            uint32_t af[4][4];
            #pragma unroll
            for (int mi = 0; mi < 4; mi++) {
                uint32_t addr = aS + a_lm_off + (uint32_t)((mi * 16 * APADH + k16 * 16) * 2);
                asm volatile("ldmatrix.sync.aligned.m8n8.x4.shared.b16 {%0,%1,%2,%3}, [%4];"
                    : "=r"(af[mi][0]), "=r"(af[mi][1]), "=r"(af[mi][2]), "=r"(af[mi][3])
                    : "r"(addr));
            }
            uint32_t bf[8][2];
            #pragma unroll
            for (int p = 0; p < 4; p++) {
                uint32_t addr = bS + b_lm_base + (uint32_t)((k16 * 16 * BPADH + p * 16) * 2);
                asm volatile("ldmatrix.sync.aligned.m8n8.x4.trans.shared.b16 {%0,%1,%2,%3}, [%4];"
                    : "=r"(bf[2 * p][0]), "=r"(bf[2 * p][1]),
                      "=r"(bf[2 * p + 1][0]), "=r"(bf[2 * p + 1][1])
                    : "r"(addr));
            }
            #pragma unroll
            for (int mi = 0; mi < 4; mi++)
                #pragma unroll
                for (int ni = 0; ni < 8; ni++)
                    mma16816(acc[mi][ni], af[mi], bf[ni]);
        }
        // no trailing barrier: top barrier of next iter orders buffer reuse
    }

    #pragma unroll
    for (int mi = 0; mi < 4; mi++) {
        int rbase = row0 + wm * 64 + mi * 16;
        int r0 = rbase + g, r1 = rbase + g + 8;
        #pragma unroll
        for (int ni = 0; ni < 8; ni++) {
            int col = col0 + wn * 64 + ni * 8 + cq * 2;
            float b0 = 0.f, b1 = 0.f;
            if (EPI >= 1) { b0 = bias[col]; b1 = bias[col + 1]; }
            float v0 = acc[mi][ni][0] + b0, v1 = acc[mi][ni][1] + b1;
            float v2 = acc[mi][ni][2] + b0, v3 = acc[mi][ni][3] + b1;
            if (EPI == 2) {
                v0 = v0 >= 0.f ? v0 : 0.01f * v0;
                v1 = v1 >= 0.f ? v1 : 0.01f * v1;
                v2 = v2 >= 0.f ? v2 : 0.01f * v2;
                v3 = v3 >= 0.f ? v3 : 0.01f * v3;
            }
            if (OUTH) {
                __half* Ch = (__half*)Cv;
                if (r0 < M) *(__half2*)(Ch + (size_t)r0 * ldc + col) = __floats2half2_rn(v0, v1);
                if (r1 < M) *(__half2*)(Ch + (size_t)r1 * ldc + col) = __floats2half2_rn(v2, v3);
            } else {
                float* C = (float*)Cv;
                if (r0 < M) *(float2*)(C + (size_t)r0 * ldc + col) = make_float2(v0, v1);
                if (r1 < M) *(float2*)(C + (size_t)r1 * ldc + col) = make_float2(v2, v3);
            }
        }
    }
}

// ---------------- fp32 -> fp16 conversion kernels ------------------------------
__global__ void f2h_kernel(const float4* __restrict__ src, uint2* __restrict__ dst,
                           long long n4) {
    long long i = (long long)blockIdx.x * blockDim.x + threadIdx.x;
    if (i < n4) {
        float4 v = src[i];
        __half2 h0 = __floats2half2_rn(v.x, v.y);
        __half2 h1 = __floats2half2_rn(v.z, v.w);
        dst[i] = make_uint2(*(uint32_t*)&h0, *(uint32_t*)&h1);
    }
}
// [K x 256] fp32 -> half into 512-wide buffer at column block (dst uint2 units)
__global__ void f2h_block512_kernel(const float4* __restrict__ src, uint2* __restrict__ dst,
                                    int n4, int cb4) {   // n4 = K*64, cb4 = colblock/4
    int i = blockIdx.x * blockDim.x + threadIdx.x;
    if (i >= n4) return;
    int row = i >> 6, c = i & 63;
    float4 v = src[i];
    __half2 h0 = __floats2half2_rn(v.x, v.y);
    __half2 h1 = __floats2half2_rn(v.z, v.w);
    dst[row * 128 + cb4 + c] = make_uint2(*(uint32_t*)&h0, *(uint32_t*)&h1);
}

// ---------------- edge machinery ----------------------------------------------
__global__ void probe_kernel(const long long* __restrict__ ei, long long Nn) {
    if (blockIdx.x == 0 && threadIdx.x == 0) {
        int ok = 1;
        for (int i = 0; i < 16; i++) {
            long long v = ei[i];
            if (v < 0 || v >= Nn) ok = 0;
        }
        g_flag[0] = ok;
        g_TOTAL[0] = 0;
    }
}
__global__ void zero_i_kernel(int* __restrict__ p, int n) {
    int i = blockIdx.x * blockDim.x + threadIdx.x;
    if (i < n) p[i] = 0;
}
__global__ void count_kernel(const int* __restrict__ ei32, const long long* __restrict__ ei64,
                             const int* __restrict__ et32, const long long* __restrict__ et64,
                             int* __restrict__ cnt, int E) {
    int e = blockIdx.x * blockDim.x + threadIdx.x;
    if (e >= E) return;
    long long dst; int r;
    if (g_flag[0]) { dst = ei64[(long long)E + e]; r = (int)et64[e]; }
    else           { dst = ei32[E + e];            r = et32[e]; }
    atomicAdd(&cnt[(int)dst * NREL + r], 1);
}
__global__ void scan_kernel(const int* __restrict__ cnt, int* __restrict__ off,
                            int* __restrict__ total, int n) {
    __shared__ int sh[256];
    __shared__ int base_sh;
    int i = blockIdx.x * 256 + threadIdx.x;
    int v = (i < n) ? cnt[i] : 0;
    sh[threadIdx.x] = v;
    __syncthreads();
    #pragma unroll
    for (int d = 1; d < 256; d <<= 1) {
        int t = (threadIdx.x >= d) ? sh[threadIdx.x - d] : 0;
        __syncthreads();
        sh[threadIdx.x] += t;
        __syncthreads();
    }
    if (threadIdx.x == 255) base_sh = atomicAdd(total, sh[255]);
    __syncthreads();
    if (i < n) off[i] = base_sh + sh[threadIdx.x] - v;
}
__global__ void copy_i_kernel(const int* __restrict__ s, int* __restrict__ d, int n) {
    int i = blockIdx.x * blockDim.x + threadIdx.x;
    if (i < n) d[i] = s[i];
}
__global__ void fill_kernel(const int* __restrict__ ei32, const long long* __restrict__ ei64,
                            const int* __restrict__ et32, const long long* __restrict__ et64,
                            int* __restrict__ cur, int* __restrict__ srcidx, int E) {
    int e = blockIdx.x * blockDim.x + threadIdx.x;
    if (e >= E) return;
    long long src, dst; int r;
    if (g_flag[0]) { src = ei64[e]; dst = ei64[(long long)E + e]; r = (int)et64[e]; }
    else           { src = ei32[e]; dst = ei32[E + e];            r = et32[e]; }
    int p = atomicAdd(&cur[(int)dst * NREL + r], 1);
    srcidx[p] = (int)src;
}

// ---------------- fused gather (fp16 msgs) + mean + fp32 root -> fp16 X --------
__global__ void gather_kernel(const int* __restrict__ srcidx, const int* __restrict__ off,
                              const int* __restrict__ cnt, const float* __restrict__ TR,
                              const __half* __restrict__ TM, __half* __restrict__ Xh, int Nn) {
    int node = (blockIdx.x * blockDim.x + threadIdx.x) >> 5;
    int lane = threadIdx.x & 31;
    if (node >= Nn) return;

    float s[2][8];
    #pragma unroll
    for (int r = 0; r < 2; r++)
        #pragma unroll
        for (int q = 0; q < 8; q++) s[r][q] = 0.f;

    #pragma unroll
    for (int r = 0; r < 2; r++) {
        const int base = off[node * 2 + r];
        const int n    = cnt[node * 2 + r];
        const size_t coloff = (size_t)r * 256 + lane * 8;
        int e = 0;
        for (; e + 1 < n; e += 2) {
            int s0 = srcidx[base + e], s1 = srcidx[base + e + 1];
            uint4 u0 = *(const uint4*)(TM + (size_t)s0 * 512 + coloff);
            uint4 u1 = *(const uint4*)(TM + (size_t)s1 * 512 + coloff);
            const __half2* h0 = (const __half2*)&u0;
            const __half2* h1 = (const __half2*)&u1;
            #pragma unroll
            for (int q = 0; q < 4; q++) {
                float2 a = __half22float2(h0[q]);
                float2 b = __half22float2(h1[q]);
                s[r][q * 2]     += a.x + b.x;
                s[r][q * 2 + 1] += a.y + b.y;
            }
        }
        if (e < n) {
            int s0 = srcidx[base + e];
            uint4 u0 = *(const uint4*)(TM + (size_t)s0 * 512 + coloff);
            const __half2* h0 = (const __half2*)&u0;
            #pragma unroll
            for (int q = 0; q < 4; q++) {
                float2 a = __half22float2(h0[q]);
                s[r][q * 2]     += a.x;
                s[r][q * 2 + 1] += a.y;
            }
        }
    }
    int c0 = cnt[node * 2], c1 = cnt[node * 2 + 1];
    float inv0 = 1.0f / (float)(c0 > 1 ? c0 : 1);
    float inv1 = 1.0f / (float)(c1 > 1 ? c1 : 1);
    const float4* tr = (const float4*)(TR + (size_t)node * 256) + lane * 2;
    float4 t0 = tr[0], t1 = tr[1];
    __half2 o[4];
    o[0] = __floats2half2_rn(t0.x + s[0][0] * inv0 + s[1][0] * inv1,
                             t0.y + s[0][1] * inv0 + s[1][1] * inv1);
    o[1] = __floats2half2_rn(t0.z + s[0][2] * inv0 + s[1][2] * inv1,
                             t0.w + s[0][3] * inv0 + s[1][3] * inv1);
    o[2] = __floats2half2_rn(t1.x + s[0][4] * inv0 + s[1][4] * inv1,
                             t1.y + s[0][5] * inv0 + s[1][5] * inv1);
    o[3] = __floats2half2_rn(t1.z + s[0][6] * inv0 + s[1][6] * inv1,
                             t1.w + s[0][7] * inv0 + s[1][7] * inv1);
    *(uint4*)(Xh + (size_t)node * 256 + lane * 8) = *(uint4*)o;
}

// ---------------- head --------------------------------------------------------
__global__ void head_kernel(const float* __restrict__ H, const float* __restrict__ W,
                            const float* __restrict__ b, float* __restrict__ out, int Nn) {
    int w = (blockIdx.x * blockDim.x + threadIdx.x) >> 5;
    int lane = threadIdx.x & 31;
    if (w >= Nn) return;
    const float4* h = (const float4*)(H + (long long)w * DHID);
    float d0 = 0.f, d1 = 0.f;
    #pragma unroll
    for (int q = 0; q < 2; q++) {
        float4 hv = h[lane * 2 + q];
        int kbase = lane * 8 + q * 4;
        float4 w01 = ((const float4*)W)[kbase / 2];
        float4 w23 = ((const float4*)W)[kbase / 2 + 1];
        d0 += hv.x * w01.x + hv.y * w01.z + hv.z * w23.x + hv.w * w23.z;
        d1 += hv.x * w01.y + hv.y * w01.w + hv.z * w23.y + hv.w * w23.w;
    }
    #pragma unroll
    for (int off = 16; off > 0; off >>= 1) {
        d0 += __shfl_xor_sync(0xffffffffu, d0, off);
        d1 += __shfl_xor_sync(0xffffffffu, d1, off);
    }
    if (lane == 0) {
        d0 += b[0]; d1 += b[1];
        float m = fmaxf(d0, d1);
        float e0 = expf(d0 - m), e1 = expf(d1 - m);
        float s = e0 + e1;
        out[(long long)w * 2]     = e0 / s;
        out[(long long)w * 2 + 1] = e1 / s;
    }
}

// ---------------- launch ------------------------------------------------------
extern "C" void kernel_launch(void* const* d_in, const int* in_sizes, int n_in,
                              void* d_out, int out_size) {
    const float* x     = (const float*)d_in[0];
    const void*  ei    = d_in[1];
    const void*  et    = d_in[3];
    const float* fc1_W = (const float*)d_in[4];
    const float* fc1_b = (const float*)d_in[5];
    const float* r1_w  = (const float*)d_in[6];
    const float* r1_rt = (const float*)d_in[7];
    const float* r1_b  = (const float*)d_in[8];
    const float* r2_w  = (const float*)d_in[9];
    const float* r2_rt = (const float*)d_in[10];
    const float* r2_b  = (const float*)d_in[11];
    const float* fc2_W = (const float*)d_in[12];
    const float* fc2_b = (const float*)d_in[13];
    const float* out_W = (const float*)d_in[14];
    const float* out_b = (const float*)d_in[15];

    int Nn = in_sizes[0] / DIN;   // 50000
    int E  = in_sizes[3];         // 800000

    float *H1buf, *T, *Xbuf, *F, *RWf;
    int *CNT, *OFF, *CUR, *SRC, *TOT;
    cudaGetSymbolAddress((void**)&H1buf, g_H1);
    cudaGetSymbolAddress((void**)&T,     g_T);
    cudaGetSymbolAddress((void**)&Xbuf,  g_X);
    cudaGetSymbolAddress((void**)&F,     g_F);
    cudaGetSymbolAddress((void**)&RWf,   g_RW);
    cudaGetSymbolAddress((void**)&CNT,   g_CNT);
    cudaGetSymbolAddress((void**)&OFF,   g_OFF);
    cudaGetSymbolAddress((void**)&CUR,   g_CUR);
    cudaGetSymbolAddress((void**)&SRC,   g_SRC);
    cudaGetSymbolAddress((void**)&TOT,   g_TOTAL);

    __half* RW  = (__half*)RWf;
    __half* XH  = (__half*)H1buf;                          // rounded x [N,768]
    __half* H1f = XH + (size_t)MAXN * 768;                 // fc1 out [N,768]
    float*  TR  = T;                                       // root fp32 [N,256]
    __half* TM  = (__half*)(T + (size_t)MAXN * 256);       // msgs [N,512]
    __half* Xh  = (__half*)Xbuf;                           // layer out [N,256]

    cudaFuncSetAttribute(gemm_f16_kernel<2, 1>, cudaFuncAttributeMaxDynamicSharedMemorySize, GEMM_SMEM);
    cudaFuncSetAttribute(gemm_f16_kernel<1, 0>, cudaFuncAttributeMaxDynamicSharedMemorySize, GEMM_SMEM);
    cudaFuncSetAttribute(gemm_f16_kernel<0, 1>, cudaFuncAttributeMaxDynamicSharedMemorySize, GEMM_SMEM);
    cudaFuncSetAttribute(gemm_f16_kernel<2, 0>, cudaFuncAttributeMaxDynamicSharedMemorySize, GEMM_SMEM);

    const int*       ei32 = (const int*)ei;
    const long long* ei64 = (const long long*)ei;
    const int*       et32 = (const int*)et;
    const long long* et64 = (const long long*)et;

    int NC = Nn * NREL;   // 100000
    int mb = (Nn + 127) / 128;            // 391
    long long x4 = (long long)Nn * DIN / 4;

    // Launch order: 6th launch (ncu -s 5 -c 1) = fc1 GEMM.
    probe_kernel<<<1, 32>>>(ei64, (long long)Nn);
    zero_i_kernel<<<(NC + 255) / 256, 256>>>(CNT, NC);
    f2h_kernel<<<(unsigned)((x4 + 255) / 256), 256>>>((const float4*)x, (uint2*)XH, x4);
    f2h_kernel<<<(589824 / 4 + 255) / 256, 256>>>((const float4*)fc1_W, (uint2*)(RW + OFF_FC1), 589824 / 4);
    count_kernel<<<(E + 255) / 256, 256>>>(ei32, ei64, et32, et64, CNT, E);

    // ---- fc1: H1f = half(leaky(XH @ fc1_W + b)) ----  (launch #6 — profiled)
    gemm_f16_kernel<2, 1><<<dim3(mb, 3), 256, GEMM_SMEM>>>(XH, RW + OFF_FC1, H1f, fc1_b, Nn, DIN, DIN, DIN);

    // ---- rest of CSR build + weight conversion ----
    scan_kernel<<<(NC + 255) / 256, 256>>>(CNT, OFF, TOT, NC);
    copy_i_kernel<<<(NC + 255) / 256, 256>>>(OFF, CUR, NC);
    fill_kernel<<<(E + 255) / 256, 256>>>(ei32, ei64, et32, et64, CUR, SRC, E);
    f2h_kernel<<<(196608 / 4 + 255) / 256, 256>>>((const float4*)r1_rt, (uint2*)(RW + OFF_WR1), 196608 / 4);
    f2h_block512_kernel<<<(49152 + 255) / 256, 256>>>((const float4*)r1_w,                (uint2*)(RW + OFF_WM1), 49152, 0);
    f2h_block512_kernel<<<(49152 + 255) / 256, 256>>>((const float4*)(r1_w + DIN * DHID), (uint2*)(RW + OFF_WM1), 49152, 64);
    f2h_kernel<<<(65536 / 4 + 255) / 256, 256>>>((const float4*)r2_rt, (uint2*)(RW + OFF_WR2), 65536 / 4);
    f2h_block512_kernel<<<(16384 + 255) / 256, 256>>>((const float4*)r2_w,                 (uint2*)(RW + OFF_WM2), 16384, 0);
    f2h_block512_kernel<<<(16384 + 255) / 256, 256>>>((const float4*)(r2_w + DHID * DHID), (uint2*)(RW + OFF_WM2), 16384, 64);
    f2h_kernel<<<(65536 / 4 + 255) / 256, 256>>>((const float4*)fc2_W, (uint2*)(RW + OFF_FC2), 65536 / 4);

    // ---- layer-1: root fp32 (+bias) and fp16 messages; A = H1f ----
    gemm_f16_kernel<1, 0><<<dim3(mb, 1), 256, GEMM_SMEM>>>(H1f, RW + OFF_WR1, TR, r1_b, Nn, DIN, DHID, DHID);
    gemm_f16_kernel<0, 1><<<dim3(mb, 2), 256, GEMM_SMEM>>>(H1f, RW + OFF_WM1, TM, nullptr, Nn, DIN, 512, 512);
    gather_kernel<<<(Nn + 7) / 8, 256>>>(SRC, OFF, CNT, TR, TM, Xh, Nn);

    // ---- layer-2: A = Xh ----
    gemm_f16_kernel<1, 0><<<dim3(mb, 1), 256, GEMM_SMEM>>>(Xh, RW + OFF_WR2, TR, r2_b, Nn, DHID, DHID, DHID);
    gemm_f16_kernel<0, 1><<<dim3(mb, 2), 256, GEMM_SMEM>>>(Xh, RW + OFF_WM2, TM, nullptr, Nn, DHID, 512, 512);
    gather_kernel<<<(Nn + 7) / 8, 256>>>(SRC, OFF, CNT, TR, TM, Xh, Nn);

    // ---- fc2: F = leaky(Xh @ fc2_W + b), fp32 out ----
    gemm_f16_kernel<2, 0><<<dim3(mb, 1), 256, GEMM_SMEM>>>(Xh, RW + OFF_FC2, F, fc2_b, Nn, DHID, DHID, DHID);

    // ---- head + softmax ----
    head_kernel<<<(Nn + 7) / 8, 256>>>(F, out_W, out_b, (float*)d_out, Nn);
}